// round 13
// baseline (speedup 1.0000x reference)
#include <cuda_runtime.h>

#define B_N   8
#define H_IN  384
#define W_IN  384
#define HO    382
#define WO    382
#define KST   64
#define NB    9
#define HOWO  (HO * WO)

// Weights/biases in constant memory (uniform-path loads, off L1).
__constant__ float cW[NB * KST];   // 2304 B
__constant__ float cB[KST];        // 256 B

// ---- packed f32x2 helpers (Blackwell) ----
__device__ __forceinline__ unsigned long long dup2(float v) {
    unsigned long long r;
    asm("mov.b64 %0, {%1, %1};" : "=l"(r) : "f"(v));
    return r;
}
__device__ __forceinline__ unsigned long long fma2(unsigned long long a,
                                                   unsigned long long b,
                                                   unsigned long long c) {
    unsigned long long d;
    asm("fma.rn.f32x2 %0, %1, %2, %3;" : "=l"(d) : "l"(a), "l"(b), "l"(c));
    return d;
}
__device__ __forceinline__ unsigned long long mul2(unsigned long long a,
                                                   unsigned long long b) {
    unsigned long long d;
    asm("mul.rn.f32x2 %0, %1, %2;" : "=l"(d) : "l"(a), "l"(b));
    return d;
}
__device__ __forceinline__ unsigned long long add2(unsigned long long a,
                                                   unsigned long long b) {
    unsigned long long d;
    asm("add.rn.f32x2 %0, %1, %2;" : "=l"(d) : "l"(a), "l"(b));
    return d;
}
__device__ __forceinline__ void unpack2(unsigned long long d, float& lo, float& hi) {
    asm("mov.b64 {%0, %1}, %2;" : "=f"(lo), "=f"(hi) : "l"(d));
}

__device__ __forceinline__ unsigned long long cpair(const float* p) {
    return *reinterpret_cast<const unsigned long long*>(p);
}

// Block: (32, 2) = 64 threads, no smem, no barriers, no row guard
// (382 = 2 * 191). Thread = 4 consecutive output columns of one output row.
// Grid: (3, 191, 8) = 4584 blocks. launch_bounds(64, 21) -> reg cap 48:
// lets ptxas keep its preferred ~47-reg schedule (measured-best kernel time)
// instead of the degraded 40-reg schedule forced by occupancy 23.
__global__ __launch_bounds__(64, 21) void qconv_kernel(
    const float* __restrict__ x, const int* __restrict__ keys,
    float* __restrict__ out)
{
    const float c0 = 1.5707963267948966f; // pi/2

    const int bz = blockIdx.z;
    const int i  = blockIdx.y * 2 + threadIdx.y;          // 0..381 exact
    const int j0 = blockIdx.x * 128 + threadIdx.x * 4;    // mult of 4, <= 380

    const float* xb = x + bz * (H_IN * W_IN);

    // 3x6 patch block: float4 + predicated float2 per row; transform
    // (v - 0.5f) * pi/2 exactly as the reference; duplicate into f32x2 lanes.
    unsigned long long P[18];
    const bool tail_ok = (j0 <= W_IN - 6);   // false only for j0 == 380
    #pragma unroll
    for (int r = 0; r < 3; ++r) {
        const float* rp = xb + (i + r) * W_IN + j0;
        float4 v4 = *reinterpret_cast<const float4*>(rp);
        float2 v2 = tail_ok ? *reinterpret_cast<const float2*>(rp + 4)
                            : make_float2(0.f, 0.f);
        float v[6] = { v4.x, v4.y, v4.z, v4.w, v2.x, v2.y };
        #pragma unroll
        for (int c = 0; c < 6; ++c)
            P[r * 6 + c] = dup2((v[c] - 0.5f) * c0);
    }

    float best0 = -3.4e38f, best1 = -3.4e38f, best2 = -3.4e38f, best3 = -3.4e38f;
    int   bi0 = 0, bi1 = 0, bi2 = 0, bi3 = 0;

    #pragma unroll 16
    for (int sp = 0; sp < 32; ++sp) {
        // Warp-uniform constant loads: one 8B pair per weight row + bias.
        const unsigned long long bb = cpair(cB + 2 * sp);
        const unsigned long long w0 = cpair(cW + 0 * KST + 2 * sp);
        const unsigned long long w1 = cpair(cW + 1 * KST + 2 * sp);
        const unsigned long long w2 = cpair(cW + 2 * KST + 2 * sp);
        const unsigned long long w3 = cpair(cW + 3 * KST + 2 * sp);
        const unsigned long long w4 = cpair(cW + 4 * KST + 2 * sp);
        const unsigned long long w5 = cpair(cW + 5 * KST + 2 * sp);
        const unsigned long long w6 = cpair(cW + 6 * KST + 2 * sp);
        const unsigned long long w7 = cpair(cW + 7 * KST + 2 * sp);
        const unsigned long long w8 = cpair(cW + 8 * KST + 2 * sp);

        // Bit-identical summation order: (((p0*w0 + p1*w1) + ... ) + b)
        unsigned long long a0 = mul2(P[0], w0);
        unsigned long long a1 = mul2(P[1], w0);
        unsigned long long a2 = mul2(P[2], w0);
        unsigned long long a3 = mul2(P[3], w0);

        a0 = fma2(P[1],  w1, a0);  a1 = fma2(P[2],  w1, a1);
        a2 = fma2(P[3],  w1, a2);  a3 = fma2(P[4],  w1, a3);

        a0 = fma2(P[2],  w2, a0);  a1 = fma2(P[3],  w2, a1);
        a2 = fma2(P[4],  w2, a2);  a3 = fma2(P[5],  w2, a3);

        a0 = fma2(P[6],  w3, a0);  a1 = fma2(P[7],  w3, a1);
        a2 = fma2(P[8],  w3, a2);  a3 = fma2(P[9],  w3, a3);

        a0 = fma2(P[7],  w4, a0);  a1 = fma2(P[8],  w4, a1);
        a2 = fma2(P[9],  w4, a2);  a3 = fma2(P[10], w4, a3);

        a0 = fma2(P[8],  w5, a0);  a1 = fma2(P[9],  w5, a1);
        a2 = fma2(P[10], w5, a2);  a3 = fma2(P[11], w5, a3);

        a0 = fma2(P[12], w6, a0);  a1 = fma2(P[13], w6, a1);
        a2 = fma2(P[14], w6, a2);  a3 = fma2(P[15], w6, a3);

        a0 = fma2(P[13], w7, a0);  a1 = fma2(P[14], w7, a1);
        a2 = fma2(P[15], w7, a2);  a3 = fma2(P[16], w7, a3);

        a0 = fma2(P[14], w8, a0);  a1 = fma2(P[15], w8, a1);
        a2 = fma2(P[16], w8, a2);  a3 = fma2(P[17], w8, a3);

        a0 = add2(a0, bb);
        a1 = add2(a1, bb);
        a2 = add2(a2, bb);
        a3 = add2(a3, bb);

        // Argmax: pair winner first (independent of best), then one
        // best-dependent compare. Identical to sequential strict-> scan.
        const int s0 = sp * 2;
        float lo, hi;
        {
            unpack2(a0, lo, hi);
            const bool q = hi > lo;
            const float cand = q ? hi : lo;
            const int   ci   = q ? s0 + 1 : s0;
            if (cand > best0) { best0 = cand; bi0 = ci; }
        }
        {
            unpack2(a1, lo, hi);
            const bool q = hi > lo;
            const float cand = q ? hi : lo;
            const int   ci   = q ? s0 + 1 : s0;
            if (cand > best1) { best1 = cand; bi1 = ci; }
        }
        {
            unpack2(a2, lo, hi);
            const bool q = hi > lo;
            const float cand = q ? hi : lo;
            const int   ci   = q ? s0 + 1 : s0;
            if (cand > best2) { best2 = cand; bi2 = ci; }
        }
        {
            unpack2(a3, lo, hi);
            const bool q = hi > lo;
            const float cand = q ? hi : lo;
            const int   ci   = q ? s0 + 1 : s0;
            if (cand > best3) { best3 = cand; bi3 = ci; }
        }
    }

    // Decode + store: gather winning key rows directly from global (int ->
    // float conversion is exact for 0..3), float2 stores (8B-aligned:
    // j0 even; odd rows are 8-mod-16 aligned so STG.128 is NOT legal here).
    const int obase = bz * (NB * HOWO) + i * WO + j0;
    const int* k0 = keys + bi0 * NB;
    const int* k1 = keys + bi1 * NB;
    const int* k2 = keys + bi2 * NB;
    const int* k3 = keys + bi3 * NB;
    const bool hi_ok = (j0 + 3 < WO);
    #pragma unroll
    for (int k = 0; k < NB; ++k) {
        float* op = out + obase + k * HOWO;
        *reinterpret_cast<float2*>(op) =
            make_float2((float)__ldg(k0 + k), (float)__ldg(k1 + k));
        if (hi_ok)
            *reinterpret_cast<float2*>(op + 2) =
                make_float2((float)__ldg(k2 + k), (float)__ldg(k3 + k));
    }
}

extern "C" void kernel_launch(void* const* d_in, const int* in_sizes, int n_in,
                              void* d_out, int out_size) {
    const float* x    = (const float*)d_in[0];
    const float* W    = (const float*)d_in[1];
    const float* b    = (const float*)d_in[2];
    const int*   keys = (const int*)d_in[3];
    float*       out  = (float*)d_out;

    // Device-to-device async copies into constant memory (graph-capturable).
    cudaMemcpyToSymbolAsync(cW, W, NB * KST * sizeof(float), 0,
                            cudaMemcpyDeviceToDevice);
    cudaMemcpyToSymbolAsync(cB, b, KST * sizeof(float), 0,
                            cudaMemcpyDeviceToDevice);

    dim3 block(32, 2);                 // 64 threads
    dim3 grid(3, HO / 2, B_N);         // (3, 191, 8) = 4584 blocks
    qconv_kernel<<<grid, block>>>(x, keys, out);
}